// round 5
// baseline (speedup 1.0000x reference)
#include <cuda_runtime.h>
#include <cuda_bf16.h>

__device__ double g_acc[2] = {0.0, 0.0};
__device__ unsigned int g_done = 0u;

__device__ __forceinline__ float fsqrt_approx(float x) {
    float r;
    asm("sqrt.approx.f32 %0, %1;" : "=f"(r) : "f"(x));
    return r;
}

__device__ __forceinline__ float2 ldcs2(const float2* p) {
    return __ldcs(p);
}
__device__ __forceinline__ float4 ldcs4(const float4* p) {
    return __ldcs(p);
}

__global__ __launch_bounds__(256, 8) void pose_loss_kernel(
    const float* __restrict__ pp,   // pred_pose  [B,6]
    const float* __restrict__ pc,   // pred_class [B,16]
    const float* __restrict__ tp,   // target_pose[B,6]
    const float* __restrict__ tc,   // target_class[B,16]
    float* __restrict__ out,
    int B)
{
    const int stride = gridDim.x * blockDim.x;
    float pose_s = 0.f, cls_s = 0.f;

    for (int b = blockIdx.x * blockDim.x + threadIdx.x; b < B; b += stride) {
        const float L = 0.05f;
        size_t off6 = 6ull * (size_t)b;

        // class loads first: 8 independent LDG.128 streamed (read-once -> .cs)
        const float4* pc4 = (const float4*)(pc + 16ull * (size_t)b);
        const float4* tc4 = (const float4*)(tc + 16ull * (size_t)b);
        float4 x0 = ldcs4(pc4 + 0), x1 = ldcs4(pc4 + 1),
               x2 = ldcs4(pc4 + 2), x3 = ldcs4(pc4 + 3);
        float4 y0 = ldcs4(tc4 + 0), y1 = ldcs4(tc4 + 1),
               y2 = ldcs4(tc4 + 2), y3 = ldcs4(tc4 + 3);

        // pose rows: 24B, 8B-aligned -> 3x float2 each
        const float2* pp2 = (const float2*)(pp + off6);
        const float2* tp2 = (const float2*)(tp + off6);
        float2 a0 = ldcs2(pp2 + 0), a1 = ldcs2(pp2 + 1), a2 = ldcs2(pp2 + 2);
        float2 b0 = ldcs2(tp2 + 0), b1 = ldcs2(tp2 + 1), b2 = ldcs2(tp2 + 2);

        // class MSE partial
        {
            float d;
            d = x0.x - y0.x; cls_s = fmaf(d, d, cls_s);
            d = x0.y - y0.y; cls_s = fmaf(d, d, cls_s);
            d = x0.z - y0.z; cls_s = fmaf(d, d, cls_s);
            d = x0.w - y0.w; cls_s = fmaf(d, d, cls_s);
            d = x1.x - y1.x; cls_s = fmaf(d, d, cls_s);
            d = x1.y - y1.y; cls_s = fmaf(d, d, cls_s);
            d = x1.z - y1.z; cls_s = fmaf(d, d, cls_s);
            d = x1.w - y1.w; cls_s = fmaf(d, d, cls_s);
            d = x2.x - y2.x; cls_s = fmaf(d, d, cls_s);
            d = x2.y - y2.y; cls_s = fmaf(d, d, cls_s);
            d = x2.z - y2.z; cls_s = fmaf(d, d, cls_s);
            d = x2.w - y2.w; cls_s = fmaf(d, d, cls_s);
            d = x3.x - y3.x; cls_s = fmaf(d, d, cls_s);
            d = x3.y - y3.y; cls_s = fmaf(d, d, cls_s);
            d = x3.z - y3.z; cls_s = fmaf(d, d, cls_s);
            d = x3.w - y3.w; cls_s = fmaf(d, d, cls_s);
        }

        float sy1, cy1, sp1, cp1, sr1, cr1;
        __sincosf(a0.x, &sy1, &cy1);
        __sincosf(a0.y, &sp1, &cp1);
        __sincosf(a1.x, &sr1, &cr1);
        float sy2, cy2, sp2, cp2, sr2, cr2;
        __sincosf(b0.x, &sy2, &cy2);
        __sincosf(b0.y, &sp2, &cp2);
        __sincosf(b1.x, &sr2, &cr2);

        // D = R_pred - R_gt (row-major 3x3), pre-scaled by L
        float D0 = cy1*cp1                 - cy2*cp2;
        float D1 = (cy1*sp1*sr1 - sy1*cr1) - (cy2*sp2*sr2 - sy2*cr2);
        float D2 = (cy1*sp1*cr1 + sy1*sr1) - (cy2*sp2*cr2 + sy2*sr2);
        float D3 = sy1*cp1                 - sy2*cp2;
        float D4 = (sy1*sp1*sr1 + cy1*cr1) - (sy2*sp2*sr2 + cy2*cr2);
        float D5 = (sy1*sp1*cr1 - cy1*sr1) - (sy2*sp2*cr2 - cy2*sr2);
        float D6 = -sp1                    + sp2;
        float D7 = cp1*sr1                 - cp2*sr2;
        float D8 = cp1*cr1                 - cp2*cr2;
        D0 *= L; D1 *= L; D2 *= L;
        D3 *= L; D4 *= L; D5 *= L;
        D6 *= L; D7 *= L; D8 *= L;

        float dt0 = a1.y - b1.y;
        float dt1 = a2.x - b2.x;
        float dt2 = a2.y - b2.y;

        float s = 0.f;
        #pragma unroll
        for (int ix = 0; ix < 2; ix++) {
            float fx = ix ? 1.f : -1.f;
            #pragma unroll
            for (int iy = 0; iy < 2; iy++) {
                float fy = iy ? 1.f : -1.f;
                #pragma unroll
                for (int iz = 0; iz < 2; iz++) {
                    float fz = iz ? 1.f : -1.f;
                    float vx = fmaf(fx, D0, fmaf(fy, D1, fmaf(fz, D2, dt0)));
                    float vy = fmaf(fx, D3, fmaf(fy, D4, fmaf(fz, D5, dt1)));
                    float vz = fmaf(fx, D6, fmaf(fy, D7, fmaf(fz, D8, dt2)));
                    float n2 = fmaf(vx, vx, fmaf(vy, vy, vz * vz));
                    s += fsqrt_approx(n2);
                }
            }
        }
        pose_s = fmaf(s, 0.125f, pose_s);
    }

    // warp reduce
    #pragma unroll
    for (int o = 16; o > 0; o >>= 1) {
        pose_s += __shfl_down_sync(0xffffffffu, pose_s, o);
        cls_s  += __shfl_down_sync(0xffffffffu, cls_s,  o);
    }

    __shared__ float shp[8];
    __shared__ float shc[8];
    int lane = threadIdx.x & 31;
    int w    = threadIdx.x >> 5;
    if (lane == 0) { shp[w] = pose_s; shc[w] = cls_s; }
    __syncthreads();

    __shared__ bool is_last;
    if (threadIdx.x == 0) {
        float ap = 0.f, ac = 0.f;
        #pragma unroll
        for (int i = 0; i < 8; i++) { ap += shp[i]; ac += shc[i]; }
        atomicAdd(&g_acc[0], (double)ap);
        atomicAdd(&g_acc[1], (double)ac);
        __threadfence();
        unsigned int prev = atomicAdd(&g_done, 1u);
        is_last = (prev == gridDim.x - 1u);
    }
    __syncthreads();

    if (is_last && threadIdx.x == 0) {
        double pose_mean = g_acc[0] / (double)B;
        double cls_mean  = g_acc[1] / ((double)B * 16.0);
        out[0] = (float)(pose_mean + cls_mean);
        out[1] = (float)pose_mean;
        out[2] = (float)cls_mean;
        g_acc[0] = 0.0;
        g_acc[1] = 0.0;
        __threadfence();
        g_done = 0u;
    }
}

extern "C" void kernel_launch(void* const* d_in, const int* in_sizes, int n_in,
                              void* d_out, int out_size) {
    const float* pp = (const float*)d_in[0];
    const float* pc = (const float*)d_in[1];
    const float* tp = (const float*)d_in[2];
    const float* tc = (const float*)d_in[3];
    int B = in_sizes[0] / 6;

    // Persistent, balanced grid: 1024 CTAs x 256 threads x 4 rows/thread
    // covers B = 1048576 exactly; one wave at 8 CTAs/SM on 148+ SMs.
    int threads = 256;
    int blocks = 1024;
    pose_loss_kernel<<<blocks, threads>>>(pp, pc, tp, tc, (float*)d_out, B);
}

// round 6
// speedup vs baseline: 1.2912x; 1.2912x over previous
#include <cuda_runtime.h>
#include <cuda_bf16.h>

__device__ double g_acc[2] = {0.0, 0.0};
__device__ unsigned int g_done = 0u;

__device__ __forceinline__ float fsqrt_approx(float x) {
    float r;
    asm("sqrt.approx.f32 %0, %1;" : "=f"(r) : "f"(x));
    return r;
}

__global__ __launch_bounds__(256, 4) void pose_loss_kernel(
    const float* __restrict__ pp,   // pred_pose  [B,6]
    const float* __restrict__ pc,   // pred_class [B,16]
    const float* __restrict__ tp,   // target_pose[B,6]
    const float* __restrict__ tc,   // target_class[B,16]
    float* __restrict__ out,
    int B)
{
    const int stride = gridDim.x * blockDim.x;
    float pose_s = 0.f, cls_s = 0.f;

    for (int b = blockIdx.x * blockDim.x + threadIdx.x; b < B; b += stride) {
        const float L = 0.05f;
        size_t off6 = 6ull * (size_t)b;

        // ---- front-batch ALL loads (64-reg budget lets them stay in flight) ----
        const float4* pc4 = (const float4*)(pc + 16ull * (size_t)b);
        const float4* tc4 = (const float4*)(tc + 16ull * (size_t)b);
        float4 x0 = __ldcs(pc4 + 0), x1 = __ldcs(pc4 + 1),
               x2 = __ldcs(pc4 + 2), x3 = __ldcs(pc4 + 3);
        float4 y0 = __ldcs(tc4 + 0), y1 = __ldcs(tc4 + 1),
               y2 = __ldcs(tc4 + 2), y3 = __ldcs(tc4 + 3);

        const float2* pp2 = (const float2*)(pp + off6);
        const float2* tp2 = (const float2*)(tp + off6);
        float2 a0 = __ldg(pp2 + 0), a1 = __ldg(pp2 + 1), a2 = __ldg(pp2 + 2);
        float2 b0 = __ldg(tp2 + 0), b1 = __ldg(tp2 + 1), b2 = __ldg(tp2 + 2);

        // ---- trig (longest latency chain) starts while class data arrives ----
        float sy1, cy1, sp1, cp1, sr1, cr1;
        __sincosf(a0.x, &sy1, &cy1);
        __sincosf(a0.y, &sp1, &cp1);
        __sincosf(a1.x, &sr1, &cr1);
        float sy2, cy2, sp2, cp2, sr2, cr2;
        __sincosf(b0.x, &sy2, &cy2);
        __sincosf(b0.y, &sp2, &cp2);
        __sincosf(b1.x, &sr2, &cr2);

        // ---- class MSE ----
        {
            float d;
            d = x0.x - y0.x; cls_s = fmaf(d, d, cls_s);
            d = x0.y - y0.y; cls_s = fmaf(d, d, cls_s);
            d = x0.z - y0.z; cls_s = fmaf(d, d, cls_s);
            d = x0.w - y0.w; cls_s = fmaf(d, d, cls_s);
            d = x1.x - y1.x; cls_s = fmaf(d, d, cls_s);
            d = x1.y - y1.y; cls_s = fmaf(d, d, cls_s);
            d = x1.z - y1.z; cls_s = fmaf(d, d, cls_s);
            d = x1.w - y1.w; cls_s = fmaf(d, d, cls_s);
            d = x2.x - y2.x; cls_s = fmaf(d, d, cls_s);
            d = x2.y - y2.y; cls_s = fmaf(d, d, cls_s);
            d = x2.z - y2.z; cls_s = fmaf(d, d, cls_s);
            d = x2.w - y2.w; cls_s = fmaf(d, d, cls_s);
            d = x3.x - y3.x; cls_s = fmaf(d, d, cls_s);
            d = x3.y - y3.y; cls_s = fmaf(d, d, cls_s);
            d = x3.z - y3.z; cls_s = fmaf(d, d, cls_s);
            d = x3.w - y3.w; cls_s = fmaf(d, d, cls_s);
        }

        // ---- D = R_pred - R_gt, pre-scaled by L ----
        float D0 = cy1*cp1                 - cy2*cp2;
        float D1 = (cy1*sp1*sr1 - sy1*cr1) - (cy2*sp2*sr2 - sy2*cr2);
        float D2 = (cy1*sp1*cr1 + sy1*sr1) - (cy2*sp2*cr2 + sy2*sr2);
        float D3 = sy1*cp1                 - sy2*cp2;
        float D4 = (sy1*sp1*sr1 + cy1*cr1) - (sy2*sp2*sr2 + cy2*cr2);
        float D5 = (sy1*sp1*cr1 - cy1*sr1) - (sy2*sp2*cr2 - cy2*sr2);
        float D6 = -sp1                    + sp2;
        float D7 = cp1*sr1                 - cp2*sr2;
        float D8 = cp1*cr1                 - cp2*cr2;
        D0 *= L; D1 *= L; D2 *= L;
        D3 *= L; D4 *= L; D5 *= L;
        D6 *= L; D7 *= L; D8 *= L;

        float dt0 = a1.y - b1.y;
        float dt1 = a2.x - b2.x;
        float dt2 = a2.y - b2.y;

        float s = 0.f;
        #pragma unroll
        for (int ix = 0; ix < 2; ix++) {
            float fx = ix ? 1.f : -1.f;
            #pragma unroll
            for (int iy = 0; iy < 2; iy++) {
                float fy = iy ? 1.f : -1.f;
                #pragma unroll
                for (int iz = 0; iz < 2; iz++) {
                    float fz = iz ? 1.f : -1.f;
                    float vx = fmaf(fx, D0, fmaf(fy, D1, fmaf(fz, D2, dt0)));
                    float vy = fmaf(fx, D3, fmaf(fy, D4, fmaf(fz, D5, dt1)));
                    float vz = fmaf(fx, D6, fmaf(fy, D7, fmaf(fz, D8, dt2)));
                    float n2 = fmaf(vx, vx, fmaf(vy, vy, vz * vz));
                    s += fsqrt_approx(n2);
                }
            }
        }
        pose_s = fmaf(s, 0.125f, pose_s);
    }

    // warp reduce
    #pragma unroll
    for (int o = 16; o > 0; o >>= 1) {
        pose_s += __shfl_down_sync(0xffffffffu, pose_s, o);
        cls_s  += __shfl_down_sync(0xffffffffu, cls_s,  o);
    }

    __shared__ float shp[8];
    __shared__ float shc[8];
    int lane = threadIdx.x & 31;
    int w    = threadIdx.x >> 5;
    if (lane == 0) { shp[w] = pose_s; shc[w] = cls_s; }
    __syncthreads();

    __shared__ bool is_last;
    if (threadIdx.x == 0) {
        float ap = 0.f, ac = 0.f;
        #pragma unroll
        for (int i = 0; i < 8; i++) { ap += shp[i]; ac += shc[i]; }
        atomicAdd(&g_acc[0], (double)ap);
        atomicAdd(&g_acc[1], (double)ac);
        __threadfence();
        unsigned int prev = atomicAdd(&g_done, 1u);
        is_last = (prev == gridDim.x - 1u);
    }
    __syncthreads();

    if (is_last && threadIdx.x == 0) {
        double pose_mean = g_acc[0] / (double)B;
        double cls_mean  = g_acc[1] / ((double)B * 16.0);
        out[0] = (float)(pose_mean + cls_mean);
        out[1] = (float)pose_mean;
        out[2] = (float)cls_mean;
        g_acc[0] = 0.0;
        g_acc[1] = 0.0;
        __threadfence();
        g_done = 0u;
    }
}

extern "C" void kernel_launch(void* const* d_in, const int* in_sizes, int n_in,
                              void* d_out, int out_size) {
    const float* pp = (const float*)d_in[0];
    const float* pc = (const float*)d_in[1];
    const float* tp = (const float*)d_in[2];
    const float* tc = (const float*)d_in[3];
    int B = in_sizes[0] / 6;

    // Persistent grid: 4 CTAs/SM (64-reg budget) x 152 SMs.
    int threads = 256;
    int blocks = 608;
    pose_loss_kernel<<<blocks, threads>>>(pp, pc, tp, tc, (float*)d_out, B);
}